// round 2
// baseline (speedup 1.0000x reference)
#include <cuda_runtime.h>
#include <cuda_bf16.h>
#include <mma.h>

using namespace nvcuda;
typedef __nv_bfloat16 bf16;

#define Bv   1024
#define Hv   512
#define Gv   2048
#define TIN  336
#define TOUT 168
#define KB0  1600      // 3*528 padded to 32
#define KB1  3072      // 3*1024
#define KBF  1536      // 3*512
#define XCOLS 48
#define NCTA 128
#define NTHR 256
#define LDK  40        // smem bf16 row stride
#define CST  132       // C tile float stride
#define DSM  69632

// ---------------- static device scratch ----------------
__device__ __align__(128) bf16 g_We0[(size_t)Gv*KB0];
__device__ __align__(128) bf16 g_We1[(size_t)Gv*KB1];
__device__ __align__(128) bf16 g_Wd0[(size_t)Gv*KB0];
__device__ __align__(128) bf16 g_Wd1[(size_t)Gv*KB1];
__device__ __align__(128) bf16 g_Wf1[(size_t)256*KBF];
__device__ __align__(128) bf16 g_A0[(size_t)2*Bv*KB0];   // ping-pong
__device__ __align__(128) bf16 g_A1[(size_t)2*Bv*KB1];   // [h0 | h1] ping-pong
__device__ __align__(128) bf16 g_xb[(size_t)Bv*TIN*XCOLS];
__device__ __align__(128) float g_c0[Bv*Hv];
__device__ __align__(128) float g_c1[Bv*Hv];
__device__ __align__(128) float g_hid[Bv*256];
__device__ unsigned g_cnt = 0;
__device__ volatile unsigned g_gen = 0;

// ---------------- helpers ----------------
__device__ __forceinline__ void cpa16(void* s, const void* g) {
    unsigned a = (unsigned)__cvta_generic_to_shared(s);
    asm volatile("cp.async.cg.shared.global [%0], [%1], 16;" :: "r"(a), "l"(g));
}
__device__ __forceinline__ void cpcommit() { asm volatile("cp.async.commit_group;"); }
__device__ __forceinline__ void cpwait0()  { asm volatile("cp.async.wait_group 0;"); }
__device__ __forceinline__ void cpwait1()  { asm volatile("cp.async.wait_group 1;"); }
__device__ __forceinline__ float sigf(float x) { return 1.f / (1.f + __expf(-x)); }

__device__ __forceinline__ void gbar() {
    __syncthreads();
    __threadfence();
    if (threadIdx.x == 0) {
        unsigned gen = g_gen;
        if (atomicAdd(&g_cnt, 1u) == (unsigned)(gridDim.x - 1)) {
            g_cnt = 0;
            __threadfence();
            g_gen = gen + 1;
        } else {
            while (g_gen == gen) { __nanosleep(64); }
        }
        __threadfence();
    }
    __syncthreads();
}

// ---------------- LSTM cell phase: C[128 x 4gates*32] = A @ W^T, then cell ----
__device__ void cell_phase(bf16* sm, const bf16* Ag, const bf16* xov,
                           const bf16* Wg, int KB, const float* bias, float* c,
                           bf16* h0d, int h0stride, int h0off, bf16* h1d)
{
    const int tid = threadIdx.x, cta = blockIdx.x;
    const int b0 = (cta >> 4) * 128;
    const int u0 = (cta & 15) * 32;
    const int nCh = KB / 32;

    auto load_chunk = [&](int kc, int bi) {
        bf16* As = sm + bi * (2 * 128 * LDK);
        bf16* Bs = As + 128 * LDK;
        const int kb = kc * 32;
        for (int s = tid; s < 1024; s += NTHR) {
            int seg = s & 3;
            int cc = kb + seg * 8;
            if (s < 512) {
                int row = s >> 2;
                const bf16* src;
                if (xov && cc < XCOLS) src = xov + (size_t)(b0 + row) * (TIN * XCOLS) + cc;
                else                   src = Ag  + (size_t)(b0 + row) * KB + cc;
                cpa16(As + row * LDK + seg * 8, src);
            } else {
                int row = (s - 512) >> 2;
                int grow = ((row >> 5) << 9) + u0 + (row & 31);
                cpa16(Bs + row * LDK + seg * 8, Wg + (size_t)grow * KB + cc);
            }
        }
        cpcommit();
    };

    wmma::fragment<wmma::accumulator, 16, 16, 16, float> acc[4][2];
    #pragma unroll
    for (int im = 0; im < 4; im++)
        #pragma unroll
        for (int in = 0; in < 2; in++) wmma::fill_fragment(acc[im][in], 0.f);

    const int warp = tid >> 5, mi = warp >> 2, nj = warp & 3;
    load_chunk(0, 0);
    int bi = 0;
    for (int kc = 0; kc < nCh; kc++) {
        if (kc + 1 < nCh) { load_chunk(kc + 1, bi ^ 1); cpwait1(); }
        else              { cpwait0(); }
        __syncthreads();
        const bf16* As = sm + bi * (2 * 128 * LDK);
        const bf16* pa = As + (mi * 64) * LDK;
        const bf16* pb = As + 128 * LDK + (nj * 32) * LDK;
        #pragma unroll
        for (int kk = 0; kk < 32; kk += 16) {
            wmma::fragment<wmma::matrix_a, 16, 16, 16, bf16, wmma::row_major> af[4];
            wmma::fragment<wmma::matrix_b, 16, 16, 16, bf16, wmma::col_major> bfr[2];
            #pragma unroll
            for (int im = 0; im < 4; im++)
                wmma::load_matrix_sync(af[im], pa + im * 16 * LDK + kk, LDK);
            #pragma unroll
            for (int in = 0; in < 2; in++)
                wmma::load_matrix_sync(bfr[in], pb + in * 16 * LDK + kk, LDK);
            #pragma unroll
            for (int im = 0; im < 4; im++)
                #pragma unroll
                for (int in = 0; in < 2; in++)
                    wmma::mma_sync(acc[im][in], af[im], bfr[in], acc[im][in]);
        }
        __syncthreads();
        bi ^= 1;
    }

    float* Cs = (float*)sm;
    #pragma unroll
    for (int im = 0; im < 4; im++)
        #pragma unroll
        for (int in = 0; in < 2; in++)
            wmma::store_matrix_sync(Cs + (mi * 64 + im * 16) * CST + nj * 32 + in * 16,
                                    acc[im][in], CST, wmma::mem_row_major);
    __syncthreads();

    for (int idx = tid; idx < 128 * 32; idx += NTHR) {
        int r = idx >> 5, ul = idx & 31;
        int b = b0 + r, u = u0 + ul;
        float gi = Cs[r * CST + ul]      + __ldg(bias + u);
        float gf = Cs[r * CST + 32 + ul] + __ldg(bias + 512 + u);
        float gg = Cs[r * CST + 64 + ul] + __ldg(bias + 1024 + u);
        float go = Cs[r * CST + 96 + ul] + __ldg(bias + 1536 + u);
        float co = g_c0[0]; // placeholder to keep compiler calm (overwritten)
        co = c[b * Hv + u];
        float cn = sigf(gf) * co + sigf(gi) * tanhf(gg);
        float h  = sigf(go) * tanhf(cn);
        c[b * Hv + u] = cn;
        bf16 hi = __float2bfloat16(h);
        bf16 lo = __float2bfloat16(h - __bfloat162float(hi));
        bf16* d0 = h0d + (size_t)b * h0stride + h0off + 3 * u;
        d0[0] = hi; d0[1] = lo; d0[2] = hi;
        if (h1d) {
            bf16* d1 = h1d + (size_t)b * KB1 + 3 * u;
            d1[0] = hi; d1[1] = lo; d1[2] = hi;
        }
    }
    __syncthreads();
}

// ---------------- fc1: hid = relu(h1 @ W1^T + b1), tiles 128x32, 64 CTAs ----
__device__ void fc_phase(bf16* sm, const float* fb1, const bf16* A1rd)
{
    const int tid = threadIdx.x, cta = blockIdx.x;
    if (cta >= 64) return;
    const int b0 = (cta >> 3) * 128;
    const int n0 = (cta & 7) * 32;
    const int nCh = KBF / 32;

    auto load_chunk = [&](int kc, int bi) {
        bf16* As = sm + bi * (160 * LDK);
        bf16* Bs = As + 128 * LDK;
        const int kb = kc * 32;
        for (int s = tid; s < 640; s += NTHR) {
            int seg = s & 3;
            if (s < 512) {
                int row = s >> 2;
                cpa16(As + row * LDK + seg * 8,
                      A1rd + (size_t)(b0 + row) * KB1 + 1536 + kb + seg * 8);
            } else {
                int row = (s - 512) >> 2;
                cpa16(Bs + row * LDK + seg * 8,
                      g_Wf1 + (size_t)(n0 + row) * KBF + kb + seg * 8);
            }
        }
        cpcommit();
    };

    wmma::fragment<wmma::accumulator, 16, 16, 16, float> acc[2];
    wmma::fill_fragment(acc[0], 0.f);
    wmma::fill_fragment(acc[1], 0.f);
    const int warp = tid >> 5;
    load_chunk(0, 0);
    int bi = 0;
    for (int kc = 0; kc < nCh; kc++) {
        if (kc + 1 < nCh) { load_chunk(kc + 1, bi ^ 1); cpwait1(); }
        else              { cpwait0(); }
        __syncthreads();
        const bf16* As = sm + bi * (160 * LDK);
        const bf16* pa = As + warp * 16 * LDK;
        const bf16* pb = As + 128 * LDK;
        #pragma unroll
        for (int kk = 0; kk < 32; kk += 16) {
            wmma::fragment<wmma::matrix_a, 16, 16, 16, bf16, wmma::row_major> af;
            wmma::fragment<wmma::matrix_b, 16, 16, 16, bf16, wmma::col_major> bfr[2];
            wmma::load_matrix_sync(af, pa + kk, LDK);
            wmma::load_matrix_sync(bfr[0], pb + kk, LDK);
            wmma::load_matrix_sync(bfr[1], pb + 16 * LDK + kk, LDK);
            wmma::mma_sync(acc[0], af, bfr[0], acc[0]);
            wmma::mma_sync(acc[1], af, bfr[1], acc[1]);
        }
        __syncthreads();
        bi ^= 1;
    }
    float* Cs = (float*)sm;
    wmma::store_matrix_sync(Cs + warp * 16 * 36,      acc[0], 36, wmma::mem_row_major);
    wmma::store_matrix_sync(Cs + warp * 16 * 36 + 16, acc[1], 36, wmma::mem_row_major);
    __syncthreads();
    for (int idx = tid; idx < 128 * 32; idx += NTHR) {
        int r = idx >> 5, cc = idx & 31;
        float v = fmaxf(Cs[r * 36 + cc] + __ldg(fb1 + n0 + cc), 0.f);
        g_hid[(b0 + r) * 256 + n0 + cc] = v;
    }
    __syncthreads();
}

// ---------------- pred: relu(hid @ w2 + b2) -> out + feedback -----------------
__device__ void pred_phase(int t, float* out, const float* w2, const float* b2,
                           bf16* A0wr)
{
    int b = blockIdx.x * 8 + (threadIdx.x >> 5);
    int lane = threadIdx.x & 31;
    float s = 0.f;
    #pragma unroll 8
    for (int j = lane; j < 256; j += 32)
        s += __ldcg(&g_hid[b * 256 + j]) * __ldg(w2 + j);
    #pragma unroll
    for (int o = 16; o; o >>= 1) s += __shfl_down_sync(0xffffffffu, s, o);
    if (lane == 0) {
        float p = fmaxf(s + __ldg(b2), 0.f);
        out[b * TOUT + t] = p;
        bf16 hi = __float2bfloat16(p);
        bf16 lo = __float2bfloat16(p - __bfloat162float(hi));
        bf16* d = A0wr + (size_t)b * KB0;
        d[0] = hi; d[1] = lo; d[2] = hi;
    }
}

// ---------------- main persistent kernel ----------------
extern __shared__ __align__(128) unsigned char dynsm[];
__global__ void __launch_bounds__(NTHR) lstm_main(
    const float* eb0, const float* eb1, const float* db0, const float* db1,
    const float* fb1, const float* fW2, const float* fb2, float* out)
{
    bf16* sm = (bf16*)dynsm;
    const size_t A0SZ = (size_t)Bv * KB0;
    const size_t A1SZ = (size_t)Bv * KB1;

    for (int s = 0; s < TIN; s++) {
        int p = s & 1;
        cell_phase(sm, g_A0 + p * A0SZ, g_xb + (size_t)s * XCOLS, g_We0, KB0, eb0,
                   g_c0, g_A0 + (p ^ 1) * A0SZ, KB0, 48, g_A1 + (p ^ 1) * A1SZ);
        gbar();
        cell_phase(sm, g_A1 + (p ^ 1) * A1SZ, nullptr, g_We1, KB1, eb1,
                   g_c1, g_A1 + p * A1SZ, KB1, 1536, nullptr);
        gbar();
    }
    for (int td = 0; td < TOUT; td++) {
        int s = TIN + td, p = s & 1;
        cell_phase(sm, g_A0 + p * A0SZ, nullptr, g_Wd0, KB0, db0,
                   g_c0, g_A0 + (p ^ 1) * A0SZ, KB0, 48, g_A1 + (p ^ 1) * A1SZ);
        gbar();
        cell_phase(sm, g_A1 + (p ^ 1) * A1SZ, nullptr, g_Wd1, KB1, db1,
                   g_c1, g_A1 + p * A1SZ, KB1, 1536, nullptr);
        gbar();
        fc_phase(sm, fb1, g_A1 + p * A1SZ);
        gbar();
        pred_phase(td, out, fW2, fb2, g_A0 + ((p ^ 1)) * A0SZ);
        gbar();
    }
}

// ---------------- prep kernels ----------------
__global__ void prep_w(const float* Wih, const float* Whh, int which,
                       int Fin, int Fpad, int Kf, int KB, int rows)
{
    bf16* dst = (which == 0) ? g_We0 : (which == 1) ? g_We1 :
                (which == 2) ? g_Wd0 : (which == 3) ? g_Wd1 : g_Wf1;
    size_t tot = (size_t)rows * KB;
    size_t stride = (size_t)gridDim.x * blockDim.x;
    for (size_t e = (size_t)blockIdx.x * blockDim.x + threadIdx.x; e < tot; e += stride) {
        int col = (int)(e % KB);
        int g = (int)(e / KB);
        float v = 0.f;
        int inrange = (col < 3 * Kf);
        int k = col / 3, slot = col - 3 * k;
        if (inrange) {
            if (k < Fin)       v = Wih[(size_t)g * Fin + k];
            else if (k < Fpad) v = 0.f;
            else               v = Whh[(size_t)g * Hv + (k - Fpad)];
        }
        bf16 hi = __float2bfloat16(v);
        bf16 lo = __float2bfloat16(v - __bfloat162float(hi));
        dst[e] = (!inrange) ? __float2bfloat16(0.f) : ((slot == 2) ? lo : hi);
    }
}

__global__ void prep_x(const float* x)
{
    size_t tot = (size_t)Bv * TIN * XCOLS;
    size_t stride = (size_t)gridDim.x * blockDim.x;
    for (size_t e = (size_t)blockIdx.x * blockDim.x + threadIdx.x; e < tot; e += stride) {
        int col = (int)(e % XCOLS);
        size_t row = e / XCOLS;               // b*TIN + t
        int k = col / 3, slot = col - 3 * k;
        float v = x[row * 16 + k];
        bf16 hi = __float2bfloat16(v);
        bf16 lo = __float2bfloat16(v - __bfloat162float(hi));
        g_xb[e] = (slot == 1) ? lo : hi;
    }
}

__global__ void prep_zero()
{
    size_t stride = (size_t)gridDim.x * blockDim.x;
    size_t i0 = (size_t)blockIdx.x * blockDim.x + threadIdx.x;
    bf16 z = __float2bfloat16(0.f);
    for (size_t e = i0; e < (size_t)2 * Bv * KB0; e += stride) g_A0[e] = z;
    for (size_t e = i0; e < (size_t)2 * Bv * KB1; e += stride) g_A1[e] = z;
    for (size_t e = i0; e < (size_t)Bv * Hv; e += stride) { g_c0[e] = 0.f; g_c1[e] = 0.f; }
}

// ---------------- host launcher ----------------
extern "C" void kernel_launch(void* const* d_in, const int* in_sizes, int n_in,
                              void* d_out, int out_size)
{
    const float* x     = (const float*)d_in[0];
    const float* eWih0 = (const float*)d_in[1];
    const float* eWhh0 = (const float*)d_in[2];
    const float* eb0   = (const float*)d_in[3];
    const float* eWih1 = (const float*)d_in[4];
    const float* eWhh1 = (const float*)d_in[5];
    const float* eb1   = (const float*)d_in[6];
    const float* dWih0 = (const float*)d_in[7];
    const float* dWhh0 = (const float*)d_in[8];
    const float* db0   = (const float*)d_in[9];
    const float* dWih1 = (const float*)d_in[10];
    const float* dWhh1 = (const float*)d_in[11];
    const float* db1   = (const float*)d_in[12];
    const float* fW1   = (const float*)d_in[13];
    const float* fb1   = (const float*)d_in[14];
    const float* fW2   = (const float*)d_in[15];
    const float* fb2   = (const float*)d_in[16];
    float* out = (float*)d_out;

    cudaFuncSetAttribute(lstm_main, cudaFuncAttributeMaxDynamicSharedMemorySize, DSM);

    prep_zero<<<512, 256>>>();
    prep_x<<<512, 256>>>(x);
    prep_w<<<512, 256>>>(eWih0, eWhh0, 0, 16, 16, 528, KB0, Gv);
    prep_w<<<512, 256>>>(eWih1, eWhh1, 1, 512, 512, 1024, KB1, Gv);
    prep_w<<<512, 256>>>(dWih0, dWhh0, 2, 1, 16, 528, KB0, Gv);
    prep_w<<<512, 256>>>(dWih1, dWhh1, 3, 512, 512, 1024, KB1, Gv);
    prep_w<<<512, 256>>>(fW1, nullptr, 4, 512, 512, 512, KBF, 256);
    lstm_main<<<NCTA, NTHR, DSM>>>(eb0, eb1, db0, db1, fb1, fW2, fb2, out);
}